// round 13
// baseline (speedup 1.0000x reference)
#include <cuda_runtime.h>
#include <cuda_bf16.h>
#include <math.h>
#include <stdint.h>

#define BATCH   8192
#define DIM     256
#define NTOT    5376      // 256 + 1024 + 4096
#define BM      128
#define BN      128
#define NT      42        // n-tiles: 2 (L1) + 8 (L2) + 32 (L3)
#define BK      64

// dynamic smem layout (bytes); swizzled SW128 tiles, no padding
#define OFF_XSQ  0            // 128 floats
#define OFF_WSQ  512          // 128 floats
#define OFF_A    1024         // 4 chunks x 16384 = 65536 (A resident, K=256)
#define OFF_B    66560        // 3 stages x 16384 = 49152
#define STAGE_BYTES 16384
#define SMEM_TOTAL 115712     // <= 116224 -> 2 CTAs/SM

__device__ __align__(16) __nv_bfloat16 g_Xe[BATCH * DIM];   // 4.2 MB
__device__ __align__(16) __nv_bfloat16 g_We[NTOT * DIM];    // 2.75 MB
__device__ float g_xsq[BATCH];
__device__ float g_wsq[NTOT];
__device__ unsigned long long g_cand[(size_t)BATCH * NT * 4];

// ---------------------------------------------------------------------------
__device__ __forceinline__ uint32_t smem_u32(const void* p) {
    uint32_t a;
    asm("{ .reg .u64 t; cvta.to.shared.u64 t, %1; cvt.u32.u64 %0, t; }"
        : "=r"(a) : "l"(p));
    return a;
}
__device__ __forceinline__ unsigned fkey(float f) {
    unsigned u = __float_as_uint(f);
    return (u & 0x80000000u) ? ~u : (u | 0x80000000u);
}
__device__ __forceinline__ float finv(unsigned m) {
    unsigned u = (m & 0x80000000u) ? (m & 0x7fffffffu) : ~m;
    return __uint_as_float(u);
}
__device__ __forceinline__ void ins4(unsigned long long k, unsigned long long t[4]) {
    if (k < t[3]) {
        t[3] = k;
        if (t[3] < t[2]) { unsigned long long z = t[2]; t[2] = t[3]; t[3] = z; }
        if (t[2] < t[1]) { unsigned long long z = t[1]; t[1] = t[2]; t[2] = z; }
        if (t[1] < t[0]) { unsigned long long z = t[0]; t[0] = t[1]; t[1] = z; }
    }
}
// yt -> (n0, wsqOff)
__device__ __forceinline__ void yt_map(int yt, int& n0, int& wsqOff) {
    if (yt < 2)       { n0 = yt * BN;        wsqOff = 0;    }
    else if (yt < 10) { n0 = (yt - 2) * BN;  wsqOff = 256;  }
    else              { n0 = (yt - 10) * BN; wsqOff = 1280; }
}

#define CP16(d, s) \
    asm volatile("cp.async.cg.shared.global [%0], [%1], 16;" :: "r"(d), "l"(s))

#define LDSM_X4(r0, r1, r2, r3, a) \
    asm volatile("ldmatrix.sync.aligned.m8n8.x4.shared.b16 {%0,%1,%2,%3}, [%4];" \
        : "=r"(r0), "=r"(r1), "=r"(r2), "=r"(r3) : "r"(a))

#define MMA16816(d, a, b0, b1) \
    asm volatile("mma.sync.aligned.m16n8k16.row.col.f32.bf16.bf16.f32 " \
        "{%0,%1,%2,%3}, {%4,%5,%6,%7}, {%8,%9}, {%0,%1,%2,%3};" \
        : "+f"((d)[0]), "+f"((d)[1]), "+f"((d)[2]), "+f"((d)[3]) \
        : "r"((a)[0]), "r"((a)[1]), "r"((a)[2]), "r"((a)[3]), \
          "r"(b0), "r"(b1))

// ---------------------------------------------------------------------------
// conv: warp per row. 2x float4 loads, packed bf16x2 stores, shfl reduction.
// ---------------------------------------------------------------------------
__global__ void som_conv(const float* __restrict__ x,
                         const float* __restrict__ w1,
                         const float* __restrict__ w2,
                         const float* __restrict__ w3) {
    int gw = (blockIdx.x * blockDim.x + threadIdx.x) >> 5;
    int lane = threadIdx.x & 31;
    if (gw >= BATCH + NTOT) return;
    const float* src;
    __nv_bfloat16* dst;
    float* nrm;
    if (gw < BATCH) {
        src = x + (size_t)gw * DIM;
        dst = g_Xe + (size_t)gw * DIM;
        nrm = g_xsq + gw;
    } else {
        int n = gw - BATCH;
        if (n < 256)       src = w1 + (size_t)n * DIM;
        else if (n < 1280) src = w2 + (size_t)(n - 256) * DIM;
        else               src = w3 + (size_t)(n - 1280) * DIM;
        dst = g_We + (size_t)n * DIM;
        nrm = g_wsq + n;
    }
    float4 a = ((const float4*)src)[lane * 2];
    float4 b = ((const float4*)src)[lane * 2 + 1];
    __nv_bfloat162 h0 = __floats2bfloat162_rn(a.x, a.y);
    __nv_bfloat162 h1 = __floats2bfloat162_rn(a.z, a.w);
    __nv_bfloat162 h2 = __floats2bfloat162_rn(b.x, b.y);
    __nv_bfloat162 h3 = __floats2bfloat162_rn(b.z, b.w);
    uint4 pk;
    pk.x = *(unsigned*)&h0; pk.y = *(unsigned*)&h1;
    pk.z = *(unsigned*)&h2; pk.w = *(unsigned*)&h3;
    ((uint4*)dst)[lane] = pk;
    float s = a.x * a.x + a.y * a.y + a.z * a.z + a.w * a.w
            + b.x * b.x + b.y * b.y + b.z * b.z + b.w * b.w;
    #pragma unroll
    for (int o = 16; o; o >>= 1) s += __shfl_xor_sync(0xffffffffu, s, o);
    if (lane == 0) *nrm = s;
}

// ---------------------------------------------------------------------------
// main: A-resident multi-tile bf16 GEMM. Each CTA: row0 fixed, full K=256 A
// tile resident in smem (SW128 swizzle); streams B tiles for 10-11 yt values
// through a 3-stage ring (one barrier per chunk). Fused top-4 argmin per yt.
// grid = (64 row-tiles, 4 yt-groups), 256 threads, 2 CTAs/SM.
// ---------------------------------------------------------------------------
__device__ __forceinline__ void issue_B(uint32_t sb, int jj, int yt0,
                                        int tid) {
    int ytj = yt0 + (jj >> 2);
    int cj = jj & 3;
    int n0j, woj;
    yt_map(ytj, n0j, woj);
    const __nv_bfloat16* gB = g_We + (size_t)(woj + n0j) * DIM;
    uint32_t base = sb + OFF_B + (uint32_t)(jj % 3) * STAGE_BYTES;
    #pragma unroll
    for (int it = 0; it < 4; it++) {
        int idx = tid + it * 256;          // 0..1023
        int r = idx >> 3;                  // 0..127
        int g = idx & 7;                   // 16B group
        uint32_t off = (uint32_t)r * 128 + (uint32_t)((g ^ (r & 7)) << 4);
        CP16(base + off, gB + (size_t)r * DIM + cj * BK + g * 8);
    }
    asm volatile("cp.async.commit_group;" ::: "memory");
}

__global__ __launch_bounds__(256, 2)
void som_mma() {
    extern __shared__ char smem[];
    float* s_xsq = (float*)(smem + OFF_XSQ);
    float* s_wsq = (float*)(smem + OFF_WSQ);
    uint32_t sb = smem_u32(smem);

    int tid = threadIdx.x, L = tid & 31, wid = tid >> 5;
    int warp_m = wid & 3, warp_n = wid >> 2;

    const int yt_start[5] = { 0, 11, 22, 32, 42 };
    int gy = blockIdx.y;
    int yt0 = yt_start[gy];
    int G = yt_start[gy + 1] - yt0;
    int NCH = 4 * G;

    int row0 = blockIdx.x * BM;
    const __nv_bfloat16* gA = g_Xe + (size_t)row0 * DIM;

    // prologue: A (all 4 chunks, one group), then B chunk 0 and 1
    #pragma unroll
    for (int it = 0; it < 16; it++) {
        int idx = tid + it * 256;          // 0..4095
        int ch = idx >> 10;                // 0..3
        int r = (idx >> 3) & 127;
        int g = idx & 7;
        uint32_t off = (uint32_t)(ch * STAGE_BYTES) + (uint32_t)r * 128
                     + (uint32_t)((g ^ (r & 7)) << 4);
        CP16(sb + OFF_A + off, gA + (size_t)r * DIM + ch * BK + g * 8);
    }
    asm volatile("cp.async.commit_group;" ::: "memory");
    issue_B(sb, 0, yt0, tid);
    issue_B(sb, 1, yt0, tid);

    if (tid < 128) {
        s_xsq[tid] = g_xsq[row0 + tid];
        int n0f, wof; yt_map(yt0, n0f, wof);
        s_wsq[tid] = g_wsq[wof + n0f + tid];
    }

    float acc[2][8][4];
    #pragma unroll
    for (int i = 0; i < 2; i++)
        #pragma unroll
        for (int j = 0; j < 8; j++)
            #pragma unroll
            for (int q = 0; q < 4; q++) acc[i][j][q] = 0.f;

    for (int j = 0; j < NCH; j++) {
        if (j == NCH - 1)
            asm volatile("cp.async.wait_group 0;" ::: "memory");
        else
            asm volatile("cp.async.wait_group 1;" ::: "memory");
        __syncthreads();

        if (j + 2 < NCH) issue_B(sb, j + 2, yt0, tid);

        uint32_t bA = sb + OFF_A + (uint32_t)(j & 3) * STAGE_BYTES;
        uint32_t bB = sb + OFF_B + (uint32_t)(j % 3) * STAGE_BYTES;
        #pragma unroll
        for (int kk = 0; kk < 4; kk++) {
            uint32_t a[2][4];
            #pragma unroll
            for (int i = 0; i < 2; i++) {
                int row = warp_m * 32 + i * 16 + (L & 15);
                int g = kk * 2 + (L >> 4);
                uint32_t addr = bA + (uint32_t)row * 128
                              + (uint32_t)((g ^ (row & 7)) << 4);
                LDSM_X4(a[i][0], a[i][1], a[i][2], a[i][3], addr);
            }
            uint32_t b[8][2];
            #pragma unroll
            for (int jp = 0; jp < 4; jp++) {
                int n = warp_n * 64 + jp * 16 + ((L >> 4) & 1) * 8 + (L & 7);
                int g = kk * 2 + ((L >> 3) & 1);
                uint32_t addr = bB + (uint32_t)n * 128
                              + (uint32_t)((g ^ (n & 7)) << 4);
                uint32_t r0, r1, r2, r3;
                LDSM_X4(r0, r1, r2, r3, addr);
                b[2 * jp][0] = r0;     b[2 * jp][1] = r1;
                b[2 * jp + 1][0] = r2; b[2 * jp + 1][1] = r3;
            }
            #pragma unroll
            for (int i = 0; i < 2; i++)
                #pragma unroll
                for (int jx = 0; jx < 8; jx++)
                    MMA16816(acc[i][jx], a[i], b[jx][0], b[jx][1]);
        }

        if ((j & 3) == 3) {
            // ---------------- epilogue for yt = yt0 + (j>>2) ----------------
            int yt = yt0 + (j >> 2);
            int n0, wsqOff; yt_map(yt, n0, wsqOff);

            unsigned long long t4[4][4];
            #pragma unroll
            for (int r = 0; r < 4; r++)
                #pragma unroll
                for (int s = 0; s < 4; s++) t4[r][s] = ~0ull;

            #pragma unroll
            for (int i = 0; i < 2; i++) {
                #pragma unroll
                for (int half = 0; half < 2; half++) {
                    int ridx = i * 2 + half;
                    int row = warp_m * 32 + i * 16 + (L >> 2) + half * 8;
                    float xq = s_xsq[row];
                    #pragma unroll
                    for (int jx = 0; jx < 8; jx++) {
                        int nb = warp_n * 64 + jx * 8 + 2 * (L & 3);
                        float s0 = xq + s_wsq[nb]     - 2.0f * acc[i][jx][half * 2 + 0];
                        float s1 = xq + s_wsq[nb + 1] - 2.0f * acc[i][jx][half * 2 + 1];
                        unsigned long long k0 =
                            (((unsigned long long)fkey(s0)) << 32) | (unsigned)(n0 + nb);
                        unsigned long long k1 =
                            (((unsigned long long)fkey(s1)) << 32) | (unsigned)(n0 + nb + 1);
                        ins4(k0, t4[ridx]);
                        ins4(k1, t4[ridx]);
                    }
                }
            }
            // quad reduction (lanes L^1, L^2 share the same rows)
            #pragma unroll
            for (int off = 1; off < 4; off <<= 1) {
                #pragma unroll
                for (int r = 0; r < 4; r++) {
                    unsigned long long o0 = __shfl_xor_sync(0xffffffffu, t4[r][0], off);
                    unsigned long long o1 = __shfl_xor_sync(0xffffffffu, t4[r][1], off);
                    unsigned long long o2 = __shfl_xor_sync(0xffffffffu, t4[r][2], off);
                    unsigned long long o3 = __shfl_xor_sync(0xffffffffu, t4[r][3], off);
                    ins4(o0, t4[r]); ins4(o1, t4[r]); ins4(o2, t4[r]); ins4(o3, t4[r]);
                }
            }
            // s_red aliases the just-consumed B stage (all warps done: barrier)
            __syncthreads();
            unsigned long long* s_red =
                (unsigned long long*)(smem + OFF_B + (j % 3) * STAGE_BYTES);
            if ((L & 3) == 0) {
                #pragma unroll
                for (int i = 0; i < 2; i++)
                    #pragma unroll
                    for (int half = 0; half < 2; half++) {
                        int ridx = i * 2 + half;
                        int row = warp_m * 32 + i * 16 + (L >> 2) + half * 8;
                        #pragma unroll
                        for (int s = 0; s < 4; s++)
                            s_red[row * 8 + warp_n * 4 + s] = t4[ridx][s];
                    }
            }
            __syncthreads();
            if (tid < 128) {
                unsigned long long m[4];
                #pragma unroll
                for (int s = 0; s < 4; s++) m[s] = s_red[tid * 8 + s];
                #pragma unroll
                for (int s = 0; s < 4; s++) ins4(s_red[tid * 8 + 4 + s], m);
                size_t gi = ((size_t)(row0 + tid) * NT + yt) * 4;
                #pragma unroll
                for (int s = 0; s < 4; s++) g_cand[gi + s] = m[s];
                // reload wsq for next yt (readers protected by later barriers)
                if (yt + 1 < yt_start[gy + 1]) {
                    int n0n, won; yt_map(yt + 1, n0n, won);
                    s_wsq[tid] = g_wsq[won + n0n + tid];
                }
            }
            // reset accumulators for next yt
            #pragma unroll
            for (int i = 0; i < 2; i++)
                #pragma unroll
                for (int jx = 0; jx < 8; jx++)
                    #pragma unroll
                    for (int q = 0; q < 4; q++) acc[i][jx][q] = 0.f;
        }
    }
}

// ---------------------------------------------------------------------------
// stage2: one warp per (level,row). Warp-parallel exact fp32 rescore of all
// candidates within thr of approx min; exact argmin + exact q_err; outputs.
// ---------------------------------------------------------------------------
__global__ void som_stage2(const float* __restrict__ x,
                           const float* __restrict__ w1,
                           const float* __restrict__ w2,
                           const float* __restrict__ w3,
                           float* __restrict__ out) {
    int gw = (blockIdx.x * blockDim.x + threadIdx.x) >> 5;
    int lane = threadIdx.x & 31;
    if (gw >= 3 * BATCH) return;
    int level = gw / BATCH;
    int row = gw - level * BATCH;

    const int t0s[3]  = { 0, 2, 10 };
    const int nts[3]  = { 2, 8, 32 };
    const int offs[3] = { 0, 256, 1280 };
    int t0 = t0s[level], ncand = nts[level] * 4;
    const float* w = (level == 0) ? w1 : ((level == 1) ? w2 : w3);
    int side = 16 << level;

    size_t cbase = ((size_t)row * NT + t0) * 4;
    unsigned long long cand[4] = { ~0ull, ~0ull, ~0ull, ~0ull };
    #pragma unroll
    for (int ci = 0; ci < 4; ci++) {
        int idx = lane * 4 + ci;
        if (idx < ncand) cand[ci] = g_cand[cbase + idx];
    }

    const float INF = __int_as_float(0x7f800000);
    float m = INF;
    #pragma unroll
    for (int ci = 0; ci < 4; ci++)
        if (cand[ci] != ~0ull) m = fminf(m, finv((unsigned)(cand[ci] >> 32)));
    #pragma unroll
    for (int o = 16; o; o >>= 1) m = fminf(m, __shfl_xor_sync(0xffffffffu, m, o));
    float thr = m + 1.6f;

    float xsq = g_xsq[row];
    const float4* xr = (const float4*)(x + (size_t)row * DIM);
    float4 xa = xr[lane], xb = xr[lane + 32];

    unsigned long long ebest = ~0ull;
    float ed2 = 0.f;
    #pragma unroll
    for (int ci = 0; ci < 4; ci++) {
        bool pass = (cand[ci] != ~0ull) &&
                    (finv((unsigned)(cand[ci] >> 32)) <= thr);
        unsigned mask = __ballot_sync(0xffffffffu, pass);
        while (mask) {
            int src = __ffs(mask) - 1;
            mask &= mask - 1;
            unsigned long long k = __shfl_sync(0xffffffffu, cand[ci], src);
            int n = (int)(k & 0xffffffffu);
            const float4* wr = (const float4*)(w + (size_t)n * DIM);
            float4 wa = wr[lane], wb = wr[lane + 32];
            float dot = xa.x * wa.x + xa.y * wa.y + xa.z * wa.z + xa.w * wa.w
                      + xb.x * wb.x + xb.y * wb.y + xb.z * wb.z + xb.w * wb.w;
            float dx0 = xa.x - wa.x, dx1 = xa.y - wa.y,
                  dx2 = xa.z - wa.z, dx3 = xa.w - wa.w;
            float dy0 = xb.x - wb.x, dy1 = xb.y - wb.y,
                  dy2 = xb.z - wb.z, dy3 = xb.w - wb.w;
            float df = dx0 * dx0 + dx1 * dx1 + dx2 * dx2 + dx3 * dx3
                     + dy0 * dy0 + dy1 * dy1 + dy2 * dy2 + dy3 * dy3;
            #pragma unroll
            for (int o = 16; o; o >>= 1) {
                dot += __shfl_xor_sync(0xffffffffu, dot, o);
                df  += __shfl_xor_sync(0xffffffffu, df, o);
            }
            float sc = xsq + g_wsq[offs[level] + n] - 2.0f * dot;
            unsigned long long ek =
                (((unsigned long long)fkey(sc)) << 32) | (unsigned)n;
            if (ek < ebest) { ebest = ek; ed2 = df; }
        }
    }

    if (lane == 0) {
        int n = (int)(ebest & 0xffffffffu);
        out[level * (2 * BATCH) + 2 * row + 0] = (float)(n / side);
        out[level * (2 * BATCH) + 2 * row + 1] = (float)(n % side);
        out[3 * (2 * BATCH) + level * BATCH + row] = sqrtf(ed2 < 0.f ? 0.f : ed2);
    }
}

// ---------------------------------------------------------------------------
extern "C" void kernel_launch(void* const* d_in, const int* in_sizes, int n_in,
                              void* d_out, int out_size) {
    const float *x = nullptr, *w1 = nullptr, *w2 = nullptr, *w3 = nullptr;
    for (int i = 0; i < n_in; i++) {
        switch (in_sizes[i]) {
            case 8192 * 256: x  = (const float*)d_in[i]; break;
            case 256 * 256:  w1 = (const float*)d_in[i]; break;
            case 1024 * 256: w2 = (const float*)d_in[i]; break;
            case 4096 * 256: w3 = (const float*)d_in[i]; break;
            default: break;
        }
    }
    float* out = (float*)d_out;

    cudaFuncSetAttribute(som_mma, cudaFuncAttributeMaxDynamicSharedMemorySize,
                         SMEM_TOTAL);

    som_conv<<<(BATCH + NTOT + 7) / 8, 256>>>(x, w1, w2, w3);

    dim3 grid(BATCH / BM, 4);
    som_mma<<<grid, 256, SMEM_TOTAL>>>();

    som_stage2<<<3 * BATCH / 8, 256>>>(x, w1, w2, w3, out);
}

// round 14
// speedup vs baseline: 1.2504x; 1.2504x over previous
#include <cuda_runtime.h>
#include <cuda_fp16.h>
#include <math.h>
#include <stdint.h>

#define BATCH   8192
#define DIM     256
#define NTOT    5376      // 256 + 1024 + 4096
#define BM      128
#define BN      128
#define NT      42        // n-tiles: 2 (L1) + 8 (L2) + 32 (L3)
#define BK      64
#define NCHUNK  4         // 256 / 64
#define ASTR    72        // padded smem row stride in fp16 (144B)

// dynamic smem layout (bytes)
#define OFF_XSQ  0          // 128 floats
#define OFF_WSQ  512        // 128 floats
#define OFF_TILE 1024       // 6 buffers: A0 A1 A2 B0 B1 B2
#define TILE_BYTES 18432
#define OFF_RED  (OFF_TILE + TILE_BYTES)   // aliases A1 (dead after chunk 1)
#define SMEM_TOTAL (OFF_TILE + 6 * TILE_BYTES)   // 111616 -> 2 CTAs/SM

__device__ __align__(16) __half g_Xe[BATCH * DIM];   // 4.2 MB
__device__ __align__(16) __half g_We[NTOT * DIM];    // 2.75 MB
__device__ float g_xsq[BATCH];
__device__ float g_wsq[NTOT];
__device__ unsigned long long g_cand[(size_t)BATCH * NT * 4];

// ---------------------------------------------------------------------------
__device__ __forceinline__ uint32_t smem_u32(const void* p) {
    uint32_t a;
    asm("{ .reg .u64 t; cvta.to.shared.u64 t, %1; cvt.u32.u64 %0, t; }"
        : "=r"(a) : "l"(p));
    return a;
}
__device__ __forceinline__ unsigned fkey(float f) {
    unsigned u = __float_as_uint(f);
    return (u & 0x80000000u) ? ~u : (u | 0x80000000u);
}
__device__ __forceinline__ float finv(unsigned m) {
    unsigned u = (m & 0x80000000u) ? (m & 0x7fffffffu) : ~m;
    return __uint_as_float(u);
}
__device__ __forceinline__ void ins4(unsigned long long k, unsigned long long t[4]) {
    if (k < t[3]) {
        t[3] = k;
        if (t[3] < t[2]) { unsigned long long z = t[2]; t[2] = t[3]; t[3] = z; }
        if (t[2] < t[1]) { unsigned long long z = t[1]; t[1] = t[2]; t[2] = z; }
        if (t[1] < t[0]) { unsigned long long z = t[0]; t[0] = t[1]; t[1] = z; }
    }
}

#define CP16(d, s) \
    asm volatile("cp.async.cg.shared.global [%0], [%1], 16;" :: "r"(d), "l"(s))

#define LDSM_X4(r0, r1, r2, r3, a) \
    asm volatile("ldmatrix.sync.aligned.m8n8.x4.shared.b16 {%0,%1,%2,%3}, [%4];" \
        : "=r"(r0), "=r"(r1), "=r"(r2), "=r"(r3) : "r"(a))

// fp16-accumulate HMMA: C/D fragment = 2 regs (4 halves)
#define MMA16816H(d, a, b0, b1) \
    asm volatile("mma.sync.aligned.m16n8k16.row.col.f16.f16.f16.f16 " \
        "{%0,%1}, {%2,%3,%4,%5}, {%6,%7}, {%0,%1};" \
        : "+r"((d)[0]), "+r"((d)[1]) \
        : "r"((a)[0]), "r"((a)[1]), "r"((a)[2]), "r"((a)[3]), \
          "r"(b0), "r"(b1))

// ---------------------------------------------------------------------------
// conv: warp per row. 2x float4 loads, packed fp16x2 stores, shfl reduction.
// ---------------------------------------------------------------------------
__global__ void som_conv(const float* __restrict__ x,
                         const float* __restrict__ w1,
                         const float* __restrict__ w2,
                         const float* __restrict__ w3) {
    int gw = (blockIdx.x * blockDim.x + threadIdx.x) >> 5;
    int lane = threadIdx.x & 31;
    if (gw >= BATCH + NTOT) return;
    const float* src;
    __half* dst;
    float* nrm;
    if (gw < BATCH) {
        src = x + (size_t)gw * DIM;
        dst = g_Xe + (size_t)gw * DIM;
        nrm = g_xsq + gw;
    } else {
        int n = gw - BATCH;
        if (n < 256)       src = w1 + (size_t)n * DIM;
        else if (n < 1280) src = w2 + (size_t)(n - 256) * DIM;
        else               src = w3 + (size_t)(n - 1280) * DIM;
        dst = g_We + (size_t)n * DIM;
        nrm = g_wsq + n;
    }
    float4 a = ((const float4*)src)[lane * 2];
    float4 b = ((const float4*)src)[lane * 2 + 1];
    __half2 h0 = __floats2half2_rn(a.x, a.y);
    __half2 h1 = __floats2half2_rn(a.z, a.w);
    __half2 h2 = __floats2half2_rn(b.x, b.y);
    __half2 h3 = __floats2half2_rn(b.z, b.w);
    uint4 pk;
    pk.x = *(unsigned*)&h0; pk.y = *(unsigned*)&h1;
    pk.z = *(unsigned*)&h2; pk.w = *(unsigned*)&h3;
    ((uint4*)dst)[lane] = pk;
    float s = a.x * a.x + a.y * a.y + a.z * a.z + a.w * a.w
            + b.x * b.x + b.y * b.y + b.z * b.z + b.w * b.w;
    #pragma unroll
    for (int o = 16; o; o >>= 1) s += __shfl_xor_sync(0xffffffffu, s, o);
    if (lane == 0) *nrm = s;
}

// ---------------------------------------------------------------------------
// main: fp16-acc mma.sync GEMM 128x128 tile, K=256 in 4 BK=64 chunks,
// 3-stage cp.async pipeline, one barrier per chunk, 2 CTAs/SM.
// grid = (64, 42), 256 threads (8 warps), warp grid 4(m) x 2(n).
// Fused top-4 argmin per (row, tile).
// ---------------------------------------------------------------------------
__device__ __forceinline__ void prefetch_chunk(uint32_t bA, uint32_t bB,
                                               const __half* gA,
                                               const __half* gB,
                                               int k0, int tid) {
    #pragma unroll
    for (int it = 0; it < 4; it++) {
        int idx = tid + it * 256;          // 0..1023
        int r = idx >> 3;                  // 0..127
        int g = idx & 7;                   // 16B group within 64 fp16
        uint32_t off = (uint32_t)(r * ASTR + g * 8) * 2;
        CP16(bA + off, gA + (size_t)r * DIM + k0 + g * 8);
        CP16(bB + off, gB + (size_t)r * DIM + k0 + g * 8);
    }
    asm volatile("cp.async.commit_group;" ::: "memory");
}

__global__ __launch_bounds__(256, 2)
void som_mma() {
    extern __shared__ char smem[];
    float* s_xsq = (float*)(smem + OFF_XSQ);
    float* s_wsq = (float*)(smem + OFF_WSQ);
    unsigned long long* s_red = (unsigned long long*)(smem + OFF_RED);
    uint32_t sb = smem_u32(smem);

    int tid = threadIdx.x, L = tid & 31, wid = tid >> 5;
    int warp_m = wid & 3, warp_n = wid >> 2;
    int yt = blockIdx.y;

    int n0, wsqOff;
    if (yt < 2)       { n0 = yt * BN;        wsqOff = 0;    }
    else if (yt < 10) { n0 = (yt - 2) * BN;  wsqOff = 256;  }
    else              { n0 = (yt - 10) * BN; wsqOff = 1280; }

    int row0 = blockIdx.x * BM;
    const __half* gA = g_Xe + (size_t)row0 * DIM;
    const __half* gB = g_We + (size_t)(wsqOff + n0) * DIM;

    // stage s: A at OFF_TILE + s*TILE, B at OFF_TILE + (3+s)*TILE
    prefetch_chunk(sb + OFF_TILE + 0 * TILE_BYTES,
                   sb + OFF_TILE + 3 * TILE_BYTES, gA, gB, 0 * BK, tid);
    prefetch_chunk(sb + OFF_TILE + 1 * TILE_BYTES,
                   sb + OFF_TILE + 4 * TILE_BYTES, gA, gB, 1 * BK, tid);
    prefetch_chunk(sb + OFF_TILE + 2 * TILE_BYTES,
                   sb + OFF_TILE + 5 * TILE_BYTES, gA, gB, 2 * BK, tid);

    if (tid < 128) {
        s_xsq[tid] = g_xsq[row0 + tid];
        s_wsq[tid] = g_wsq[wsqOff + n0 + tid];
    }

    uint32_t acc[2][8][2];            // fp16x2 accumulators
    #pragma unroll
    for (int i = 0; i < 2; i++)
        #pragma unroll
        for (int j = 0; j < 8; j++) { acc[i][j][0] = 0u; acc[i][j][1] = 0u; }

    #pragma unroll
    for (int c = 0; c < NCHUNK; c++) {
        if (c == 0)      asm volatile("cp.async.wait_group 2;" ::: "memory");
        else if (c == 3) asm volatile("cp.async.wait_group 0;" ::: "memory");
        else             asm volatile("cp.async.wait_group 1;" ::: "memory");
        __syncthreads();

        if (c == 1)
            prefetch_chunk(sb + OFF_TILE + 0 * TILE_BYTES,
                           sb + OFF_TILE + 3 * TILE_BYTES, gA, gB, 3 * BK, tid);

        int st = c % 3;
        uint32_t bA = sb + OFF_TILE + (uint32_t)st * TILE_BYTES;
        uint32_t bB = sb + OFF_TILE + (uint32_t)(3 + st) * TILE_BYTES;
        #pragma unroll
        for (int kk = 0; kk < 4; kk++) {
            uint32_t a[2][4];
            #pragma unroll
            for (int i = 0; i < 2; i++) {
                int row = warp_m * 32 + i * 16 + (L & 15);
                uint32_t addr = bA + (uint32_t)(row * ASTR + kk * 16 + (L >> 4) * 8) * 2;
                LDSM_X4(a[i][0], a[i][1], a[i][2], a[i][3], addr);
            }
            uint32_t b[8][2];
            #pragma unroll
            for (int jp = 0; jp < 4; jp++) {
                int n = warp_n * 64 + jp * 16 + ((L >> 4) & 1) * 8 + (L & 7);
                uint32_t koff = ((L >> 3) & 1) * 8;
                uint32_t addr = bB + (uint32_t)(n * ASTR + kk * 16 + koff) * 2;
                uint32_t r0, r1, r2, r3;
                LDSM_X4(r0, r1, r2, r3, addr);
                b[2 * jp][0] = r0;     b[2 * jp][1] = r1;
                b[2 * jp + 1][0] = r2; b[2 * jp + 1][1] = r3;
            }
            #pragma unroll
            for (int i = 0; i < 2; i++)
                #pragma unroll
                for (int j = 0; j < 8; j++)
                    MMA16816H(acc[i][j], a[i], b[j][0], b[j][1]);
        }
    }

    // ------------- epilogue: scores + per-row top-4 over this tile ----------
    unsigned long long t4[4][4];
    #pragma unroll
    for (int r = 0; r < 4; r++)
        #pragma unroll
        for (int s = 0; s < 4; s++) t4[r][s] = ~0ull;

    #pragma unroll
    for (int i = 0; i < 2; i++) {
        #pragma unroll
        for (int half = 0; half < 2; half++) {     // half = C-fragment reg
            int ridx = i * 2 + half;
            int row = warp_m * 32 + i * 16 + (L >> 2) + half * 8;
            float xq = s_xsq[row];
            #pragma unroll
            for (int j = 0; j < 8; j++) {
                int nb = warp_n * 64 + j * 8 + 2 * (L & 3);
                __half2 h = *(__half2*)&acc[i][j][half];
                float d0 = __low2float(h);
                float d1 = __high2float(h);
                float s0 = xq + s_wsq[nb]     - 2.0f * d0;
                float s1 = xq + s_wsq[nb + 1] - 2.0f * d1;
                unsigned long long k0 =
                    (((unsigned long long)fkey(s0)) << 32) | (unsigned)(n0 + nb);
                unsigned long long k1 =
                    (((unsigned long long)fkey(s1)) << 32) | (unsigned)(n0 + nb + 1);
                ins4(k0, t4[ridx]);
                ins4(k1, t4[ridx]);
            }
        }
    }

    // quad reduction (lanes L^1, L^2 share the same rows)
    #pragma unroll
    for (int off = 1; off < 4; off <<= 1) {
        #pragma unroll
        for (int r = 0; r < 4; r++) {
            unsigned long long o0 = __shfl_xor_sync(0xffffffffu, t4[r][0], off);
            unsigned long long o1 = __shfl_xor_sync(0xffffffffu, t4[r][1], off);
            unsigned long long o2 = __shfl_xor_sync(0xffffffffu, t4[r][2], off);
            unsigned long long o3 = __shfl_xor_sync(0xffffffffu, t4[r][3], off);
            ins4(o0, t4[r]); ins4(o1, t4[r]); ins4(o2, t4[r]); ins4(o3, t4[r]);
        }
    }
    if ((L & 3) == 0) {
        #pragma unroll
        for (int i = 0; i < 2; i++)
            #pragma unroll
            for (int half = 0; half < 2; half++) {
                int ridx = i * 2 + half;
                int row = warp_m * 32 + i * 16 + (L >> 2) + half * 8;
                #pragma unroll
                for (int s = 0; s < 4; s++)
                    s_red[row * 8 + warp_n * 4 + s] = t4[ridx][s];
            }
    }
    __syncthreads();

    if (tid < 128) {
        unsigned long long m[4];
        #pragma unroll
        for (int s = 0; s < 4; s++) m[s] = s_red[tid * 8 + s];
        #pragma unroll
        for (int s = 0; s < 4; s++) ins4(s_red[tid * 8 + 4 + s], m);
        size_t gi = ((size_t)(row0 + tid) * NT + yt) * 4;
        #pragma unroll
        for (int s = 0; s < 4; s++) g_cand[gi + s] = m[s];
    }
}

// ---------------------------------------------------------------------------
// stage2: one warp per (level,row). Warp-parallel exact fp32 rescore of all
// candidates within thr of approx min; exact argmin + exact q_err; outputs.
// ---------------------------------------------------------------------------
__global__ void som_stage2(const float* __restrict__ x,
                           const float* __restrict__ w1,
                           const float* __restrict__ w2,
                           const float* __restrict__ w3,
                           float* __restrict__ out) {
    int gw = (blockIdx.x * blockDim.x + threadIdx.x) >> 5;
    int lane = threadIdx.x & 31;
    if (gw >= 3 * BATCH) return;
    int level = gw / BATCH;
    int row = gw - level * BATCH;

    const int t0s[3]  = { 0, 2, 10 };
    const int nts[3]  = { 2, 8, 32 };
    const int offs[3] = { 0, 256, 1280 };
    int t0 = t0s[level], ncand = nts[level] * 4;
    const float* w = (level == 0) ? w1 : ((level == 1) ? w2 : w3);
    int side = 16 << level;

    size_t cbase = ((size_t)row * NT + t0) * 4;
    unsigned long long cand[4] = { ~0ull, ~0ull, ~0ull, ~0ull };
    #pragma unroll
    for (int ci = 0; ci < 4; ci++) {
        int idx = lane * 4 + ci;
        if (idx < ncand) cand[ci] = g_cand[cbase + idx];
    }

    const float INF = __int_as_float(0x7f800000);
    float m = INF;
    #pragma unroll
    for (int ci = 0; ci < 4; ci++)
        if (cand[ci] != ~0ull) m = fminf(m, finv((unsigned)(cand[ci] >> 32)));
    #pragma unroll
    for (int o = 16; o; o >>= 1) m = fminf(m, __shfl_xor_sync(0xffffffffu, m, o));
    float thr = m + 1.6f;

    float xsq = g_xsq[row];
    const float4* xr = (const float4*)(x + (size_t)row * DIM);
    float4 xa = xr[lane], xb = xr[lane + 32];

    unsigned long long ebest = ~0ull;
    float ed2 = 0.f;
    #pragma unroll
    for (int ci = 0; ci < 4; ci++) {
        bool pass = (cand[ci] != ~0ull) &&
                    (finv((unsigned)(cand[ci] >> 32)) <= thr);
        unsigned mask = __ballot_sync(0xffffffffu, pass);
        while (mask) {
            int src = __ffs(mask) - 1;
            mask &= mask - 1;
            unsigned long long k = __shfl_sync(0xffffffffu, cand[ci], src);
            int n = (int)(k & 0xffffffffu);
            const float4* wr = (const float4*)(w + (size_t)n * DIM);
            float4 wa = wr[lane], wb = wr[lane + 32];
            float dot = xa.x * wa.x + xa.y * wa.y + xa.z * wa.z + xa.w * wa.w
                      + xb.x * wb.x + xb.y * wb.y + xb.z * wb.z + xb.w * wb.w;
            float dx0 = xa.x - wa.x, dx1 = xa.y - wa.y,
                  dx2 = xa.z - wa.z, dx3 = xa.w - wa.w;
            float dy0 = xb.x - wb.x, dy1 = xb.y - wb.y,
                  dy2 = xb.z - wb.z, dy3 = xb.w - wb.w;
            float df = dx0 * dx0 + dx1 * dx1 + dx2 * dx2 + dx3 * dx3
                     + dy0 * dy0 + dy1 * dy1 + dy2 * dy2 + dy3 * dy3;
            #pragma unroll
            for (int o = 16; o; o >>= 1) {
                dot += __shfl_xor_sync(0xffffffffu, dot, o);
                df  += __shfl_xor_sync(0xffffffffu, df, o);
            }
            float sc = xsq + g_wsq[offs[level] + n] - 2.0f * dot;
            unsigned long long ek =
                (((unsigned long long)fkey(sc)) << 32) | (unsigned)n;
            if (ek < ebest) { ebest = ek; ed2 = df; }
        }
    }

    if (lane == 0) {
        int n = (int)(ebest & 0xffffffffu);
        out[level * (2 * BATCH) + 2 * row + 0] = (float)(n / side);
        out[level * (2 * BATCH) + 2 * row + 1] = (float)(n % side);
        out[3 * (2 * BATCH) + level * BATCH + row] = sqrtf(ed2 < 0.f ? 0.f : ed2);
    }
}

// ---------------------------------------------------------------------------
extern "C" void kernel_launch(void* const* d_in, const int* in_sizes, int n_in,
                              void* d_out, int out_size) {
    const float *x = nullptr, *w1 = nullptr, *w2 = nullptr, *w3 = nullptr;
    for (int i = 0; i < n_in; i++) {
        switch (in_sizes[i]) {
            case 8192 * 256: x  = (const float*)d_in[i]; break;
            case 256 * 256:  w1 = (const float*)d_in[i]; break;
            case 1024 * 256: w2 = (const float*)d_in[i]; break;
            case 4096 * 256: w3 = (const float*)d_in[i]; break;
            default: break;
        }
    }
    float* out = (float*)d_out;

    cudaFuncSetAttribute(som_mma, cudaFuncAttributeMaxDynamicSharedMemorySize,
                         SMEM_TOTAL);

    som_conv<<<(BATCH + NTOT + 7) / 8, 256>>>(x, w1, w2, w3);

    dim3 grid(BATCH / BM, NT);
    som_mma<<<grid, 256, SMEM_TOTAL>>>();

    som_stage2<<<3 * BATCH / 8, 256>>>(x, w1, w2, w3, out);
}